// round 2
// baseline (speedup 1.0000x reference)
#include <cuda_runtime.h>

#define EMBED  512
#define HID    512
#define G4     2048      // 4*HIDDEN
#define VOCAB  10000
#define BATCH  64
#define TSTEPS 32
#define MROWS  (TSTEPS*BATCH)   // 2048
#define KDIM   512

// ---------------- scratch (device globals: allocation-free) ----------------
__device__ float g_xs  [MROWS*EMBED];    // 4 MB   xs[t*64+b][e]
__device__ float g_xg  [MROWS*G4];       // 16 MB  x_gates (+biases)
__device__ float g_hs  [MROWS*HID];      // 4 MB   all hidden states
__device__ float g_h   [BATCH*HID];      //        current h
__device__ float g_part[32*BATCH*G4];    // 16 MB  K-split partials
__device__ unsigned g_bar;               // grid barrier counter

__device__ __forceinline__ float sigf(float x) { return 1.0f / (1.0f + __expf(-x)); }

// ---------------- kernel 1: gather xs (also resets grid-barrier counter) ----------------
// xs[0] = features; xs[t] = emb_table[captions[:, t-1]] for t in 1..31.
// captions may arrive as int32 (JAX default x64-off) or int64; detect pattern.
__global__ void gather_k(const float* __restrict__ feat,
                         const int*   __restrict__ cap32,
                         const float* __restrict__ emb)
{
    if (blockIdx.x == 0 && threadIdx.x == 0) g_bar = 0u;  // reset barrier for lstm_scan

    int idx = blockIdx.x * blockDim.x + threadIdx.x;   // float4 id, 262144 total
    int e4  = idx & (EMBED/4 - 1);                     // 0..127
    int row = idx >> 7;                                // 0..2047 = t*64+b
    int t = row >> 6, b = row & 63;
    const float4* src;
    if (t == 0) {
        src = (const float4*)(feat + b * EMBED);
    } else {
        // int64 little-endian: odd 32-bit words are zero (values in [0,10000))
        bool i64 = (cap32[1] == 0 && cap32[3] == 0 && cap32[5] == 0 && cap32[7] == 0);
        int ci = b * TSTEPS + (t - 1);
        int v  = i64 ? cap32[2 * ci] : cap32[ci];
        src = (const float4*)(emb + (long)v * EMBED);
    }
    ((float4*)g_xs)[idx] = src[e4];
}

// ---------------- kernels 2 & 4: tiled fp32 GEMM (NT: C = A * B^T) ----------------
// 128x128 tile, BK=16, 256 threads, 8x8 microtile.
// MODE 0: A=g_xs, C=g_xg, bias = b_ih + b_hh.          (N = 2048)
// MODE 1: A=g_hs, C=out (permuted (b,t,v)), bias=b_fc. (N = 10000, guarded)
template<int BROWS, int MODE>
__global__ __launch_bounds__(256)
void gemm128(const float* __restrict__ Bm,
             const float* __restrict__ ba,
             const float* __restrict__ bb,
             float* __restrict__ outp)
{
    __shared__ float As[16][132];
    __shared__ float Bs[16][132];
    const float* __restrict__ A = (MODE == 0) ? g_xs : g_hs;

    const int tid = threadIdx.x;
    const int m0 = blockIdx.y * 128;
    const int n0 = blockIdx.x * 128;
    const int tm = (tid >> 4) << 3;
    const int tn = (tid & 15) << 3;

    float acc[8][8];
#pragma unroll
    for (int i = 0; i < 8; i++)
#pragma unroll
        for (int j = 0; j < 8; j++) acc[i][j] = 0.0f;

    for (int k0 = 0; k0 < KDIM; k0 += 16) {
#pragma unroll
        for (int r = 0; r < 2; r++) {
            int q  = tid + r * 256;
            int mm = q >> 2;
            int kq = (q & 3) << 2;
            float4 v = *(const float4*)&A[(size_t)(m0 + mm) * KDIM + k0 + kq];
            As[kq + 0][mm] = v.x; As[kq + 1][mm] = v.y;
            As[kq + 2][mm] = v.z; As[kq + 3][mm] = v.w;
            float4 u = make_float4(0.f, 0.f, 0.f, 0.f);
            if ((BROWS & 127) == 0 || (n0 + mm) < BROWS)
                u = *(const float4*)&Bm[(size_t)(n0 + mm) * KDIM + k0 + kq];
            Bs[kq + 0][mm] = u.x; Bs[kq + 1][mm] = u.y;
            Bs[kq + 2][mm] = u.z; Bs[kq + 3][mm] = u.w;
        }
        __syncthreads();
#pragma unroll
        for (int k = 0; k < 16; k++) {
            float a[8], b[8];
            *(float4*)&a[0] = *(const float4*)&As[k][tm];
            *(float4*)&a[4] = *(const float4*)&As[k][tm + 4];
            *(float4*)&b[0] = *(const float4*)&Bs[k][tn];
            *(float4*)&b[4] = *(const float4*)&Bs[k][tn + 4];
#pragma unroll
            for (int i = 0; i < 8; i++)
#pragma unroll
                for (int j = 0; j < 8; j++)
                    acc[i][j] = fmaf(a[i], b[j], acc[i][j]);
        }
        __syncthreads();
    }

    if (MODE == 0) {
#pragma unroll
        for (int i = 0; i < 8; i++) {
            int m = m0 + tm + i;
#pragma unroll
            for (int j = 0; j < 8; j++) {
                int n = n0 + tn + j;
                g_xg[(size_t)m * G4 + n] = acc[i][j] + ba[n] + bb[n];
            }
        }
    } else {
#pragma unroll
        for (int i = 0; i < 8; i++) {
            int m = m0 + tm + i;
            int t = m >> 6, b = m & 63;
            float* orow = outp + (size_t)(b * TSTEPS + t) * VOCAB;
#pragma unroll
            for (int j = 0; j < 8; j++) {
                int n = n0 + tn + j;
                if (n < VOCAB) orow[n] = acc[i][j] + ba[n];
            }
        }
    }
}

// ---------------- grid barrier (monotonic counter, reset by gather_k) ----------------
__device__ __forceinline__ void gridbar(unsigned ncalls)
{
    __syncthreads();
    if (threadIdx.x == 0) {
        __threadfence();
        atomicAdd(&g_bar, 1u);
        unsigned tgt = ncalls * 256u;
        unsigned v;
        do {
            asm volatile("ld.acquire.gpu.u32 %0, [%1];" : "=r"(v) : "l"(&g_bar));
        } while (v < tgt);
    }
    __syncthreads();
}

// ---------------- kernel 3: persistent LSTM scan ----------------
// 256 blocks (gg in 0..7 gate-groups of 256, ks in 0..31 K-chunks of 16), 256 threads.
// __launch_bounds__(256,2) caps regs at 128 -> 2 CTAs/SM -> all 256 blocks
// co-resident on 148 SMs (296 slots): grid barrier is deadlock-free.
// W_hh slice kept in registers across all 32 steps (W_hh read from L2 exactly once).
// Per step: phase A writes deterministic K-split partials; phase B reduces + cell
// update with c resident in registers for the whole scan.
__global__ __launch_bounds__(256, 2)
void lstm_scan(const float* __restrict__ Whh)
{
    const int bx  = blockIdx.x;
    const int ks  = bx & 31;
    const int gg  = bx >> 5;
    const int tid = threadIdx.x;
    const int g   = gg * 256 + tid;
    const int kb  = ks * 16;

    float w[16];
    {
        const float4* wp = (const float4*)&Whh[(size_t)g * HID + kb];
#pragma unroll
        for (int i = 0; i < 4; i++) {
            float4 v = wp[i];
            w[4*i+0] = v.x; w[4*i+1] = v.y; w[4*i+2] = v.z; w[4*i+3] = v.w;
        }
    }

    __shared__ float hs_s[16][68];   // [k][b], row stride 272B (16B multiple)

    const bool docell = (tid < 128);
    const int cell = bx * 128 + tid;        // 256 blocks * 128 = 32768 cells
    const int cb = cell >> 9;               // batch
    const int cj = cell & 511;              // hidden index
    float c_reg = 0.0f;
    unsigned nbar = 0;

    // t = 0: gates = x_gates[0] only (h0 = 0)
    if (docell) {
        float v0 = g_xg[(size_t)cb * G4 + cj];
        float v1 = g_xg[(size_t)cb * G4 + 512  + cj];
        float v2 = g_xg[(size_t)cb * G4 + 1024 + cj];
        float v3 = g_xg[(size_t)cb * G4 + 1536 + cj];
        float i_ = sigf(v0), f_ = sigf(v1), gt = tanhf(v2), o_ = sigf(v3);
        c_reg = f_ * c_reg + i_ * gt;
        float h = o_ * tanhf(c_reg);
        g_h [cb * HID + cj] = h;
        g_hs[cb * HID + cj] = h;
    }
    gridbar(++nbar);

    for (int t = 1; t < TSTEPS; t++) {
        // ---- phase A: partial gates = h_{t-1}[:, kb:kb+16] @ Whh[g, kb:kb+16]^T
#pragma unroll
        for (int r = 0; r < 4; r++) {
            int idx = r * 256 + tid;
            int b = idx >> 4, kk = idx & 15;
            hs_s[kk][b] = g_h[b * HID + kb + kk];
        }
        __syncthreads();

        float acc[64];
#pragma unroll
        for (int b = 0; b < 64; b++) acc[b] = 0.0f;
#pragma unroll
        for (int kk = 0; kk < 16; kk++) {
            float wv = w[kk];
#pragma unroll
            for (int b4 = 0; b4 < 16; b4++) {
                float4 h4 = *(const float4*)&hs_s[kk][b4 * 4];
                acc[b4*4+0] = fmaf(wv, h4.x, acc[b4*4+0]);
                acc[b4*4+1] = fmaf(wv, h4.y, acc[b4*4+1]);
                acc[b4*4+2] = fmaf(wv, h4.z, acc[b4*4+2]);
                acc[b4*4+3] = fmaf(wv, h4.w, acc[b4*4+3]);
            }
        }
#pragma unroll
        for (int b = 0; b < 64; b++)
            g_part[(size_t)(ks * 64 + b) * G4 + g] = acc[b];

        gridbar(++nbar);

        // ---- phase B: reduce partials + cell update
        if (docell) {
            float v[4];
#pragma unroll
            for (int s = 0; s < 4; s++) {
                float sum = g_xg[(size_t)(t * 64 + cb) * G4 + s * 512 + cj];
#pragma unroll
                for (int p = 0; p < 32; p++)
                    sum += g_part[(size_t)(p * 64 + cb) * G4 + s * 512 + cj];
                v[s] = sum;
            }
            float i_ = sigf(v[0]), f_ = sigf(v[1]), gt = tanhf(v[2]), o_ = sigf(v[3]);
            c_reg = f_ * c_reg + i_ * gt;
            float h = o_ * tanhf(c_reg);
            g_h [cb * HID + cj] = h;
            g_hs[(size_t)(t * 64 + cb) * HID + cj] = h;
        }
        gridbar(++nbar);
    }
}

// ---------------- launch ----------------
extern "C" void kernel_launch(void* const* d_in, const int* in_sizes, int n_in,
                              void* d_out, int out_size)
{
    const float* feat = (const float*)d_in[0];
    const int*   cap  = (const int*)  d_in[1];
    const float* emb  = (const float*)d_in[2];
    const float* Wih  = (const float*)d_in[3];
    const float* Whh  = (const float*)d_in[4];
    const float* bih  = (const float*)d_in[5];
    const float* bhh  = (const float*)d_in[6];
    const float* Wfc  = (const float*)d_in[7];
    const float* bfc  = (const float*)d_in[8];
    float* out = (float*)d_out;
    (void)in_sizes; (void)n_in; (void)out_size;

    gather_k<<<1024, 256>>>(feat, cap, emb);

    gemm128<2048, 0><<<dim3(G4 / 128, MROWS / 128), 256>>>(Wih, bih, bhh, nullptr);

    lstm_scan<<<256, 256>>>(Whh);

    gemm128<10000, 1><<<dim3((VOCAB + 127) / 128, MROWS / 128), 256>>>(Wfc, bfc, nullptr, out);
}

// round 3
// speedup vs baseline: 1.4333x; 1.4333x over previous
#include <cuda_runtime.h>

#define EMBED  512
#define HID    512
#define G4     2048      // 4*HIDDEN
#define VOCAB  10000
#define BATCH  64
#define TSTEPS 32
#define MROWS  (TSTEPS*BATCH)   // 2048
#define KDIM   512

// ---------------- scratch (device globals: allocation-free) ----------------
__device__ float g_xs  [MROWS*EMBED];     // 4 MB   xs[t*64+b][e]
__device__ float g_xg  [MROWS*G4];        // 16 MB  x_gates (+biases)
__device__ float g_hs  [MROWS*HID];       // 4 MB   all hidden states (row-major, for final GEMM)
__device__ float g_hd  [2][HID*BATCH];    //        current h, TRANSPOSED [j][b], double-buffered
__device__ float g_part[4*G4*BATCH];      // 2 MB   K-window partials [ksp][row][b]
__device__ unsigned g_ctr[32*32];         // spread barrier counters (stride 128B)

__device__ __forceinline__ float sigf(float x) { return 1.0f / (1.0f + __expf(-x)); }

// ---------------- kernel 1: gather xs (also resets barrier counters) ----------------
__global__ void gather_k(const float* __restrict__ feat,
                         const int*   __restrict__ cap32,
                         const float* __restrict__ emb)
{
    if (blockIdx.x == 0) {
        for (int i = threadIdx.x; i < 32 * 32; i += 256) g_ctr[i] = 0u;
    }

    int idx = blockIdx.x * blockDim.x + threadIdx.x;   // float4 id, 262144 total
    int e4  = idx & (EMBED/4 - 1);                     // 0..127
    int row = idx >> 7;                                // 0..2047 = t*64+b
    int t = row >> 6, b = row & 63;
    const float4* src;
    if (t == 0) {
        src = (const float4*)(feat + b * EMBED);
    } else {
        // int64 little-endian: odd 32-bit words are zero (values in [0,10000))
        bool i64 = (cap32[1] == 0 && cap32[3] == 0 && cap32[5] == 0 && cap32[7] == 0);
        int ci = b * TSTEPS + (t - 1);
        int v  = i64 ? cap32[2 * ci] : cap32[ci];
        src = (const float4*)(emb + (long)v * EMBED);
    }
    ((float4*)g_xs)[idx] = src[e4];
}

// ---------------- kernels 2 & 4: pipelined fp32 GEMM (NT: C = A * B^T) ----------------
// 128x128 tile, BK=16, 256 threads, 8x8 microtile.
// Register prefetch + double-buffered smem -> ONE __syncthreads per K-iter,
// global-load latency hidden under the 1024-FFMA compute block.
template<int BROWS, int MODE>
__global__ __launch_bounds__(256)
void gemm128(const float* __restrict__ Bm,
             const float* __restrict__ ba,
             const float* __restrict__ bb,
             float* __restrict__ outp)
{
    __shared__ float As[2][16][132];
    __shared__ float Bs[2][16][132];
    const float* __restrict__ A = (MODE == 0) ? g_xs : g_hs;

    const int tid = threadIdx.x;
    const int m0 = blockIdx.y * 128;
    const int n0 = blockIdx.x * 128;
    const int tm = (tid >> 4) << 3;
    const int tn = (tid & 15) << 3;
    const int mm = tid >> 2;            // 0..63
    const int kq = (tid & 3) << 2;      // 0,4,8,12

    const float* Arow0 = &A[(size_t)(m0 + mm) * KDIM + kq];
    const float* Arow1 = &A[(size_t)(m0 + 64 + mm) * KDIM + kq];
    int nr0 = n0 + mm, nr1 = n0 + 64 + mm;
    if ((BROWS & 127) != 0) {           // clamp OOB rows (values unused: epilogue guards)
        if (nr0 >= BROWS) nr0 = 0;
        if (nr1 >= BROWS) nr1 = 0;
    }
    const float* Brow0 = &Bm[(size_t)nr0 * KDIM + kq];
    const float* Brow1 = &Bm[(size_t)nr1 * KDIM + kq];

    float4 pa0, pa1, pb0, pb1;

#define LDTILE(K0) do {                                   \
        pa0 = *(const float4*)(Arow0 + (K0));             \
        pa1 = *(const float4*)(Arow1 + (K0));             \
        pb0 = *(const float4*)(Brow0 + (K0));             \
        pb1 = *(const float4*)(Brow1 + (K0));             \
    } while (0)

#define STTILE(BF) do {                                                         \
        As[BF][kq+0][mm]    = pa0.x; As[BF][kq+1][mm]    = pa0.y;               \
        As[BF][kq+2][mm]    = pa0.z; As[BF][kq+3][mm]    = pa0.w;               \
        As[BF][kq+0][64+mm] = pa1.x; As[BF][kq+1][64+mm] = pa1.y;               \
        As[BF][kq+2][64+mm] = pa1.z; As[BF][kq+3][64+mm] = pa1.w;               \
        Bs[BF][kq+0][mm]    = pb0.x; Bs[BF][kq+1][mm]    = pb0.y;               \
        Bs[BF][kq+2][mm]    = pb0.z; Bs[BF][kq+3][mm]    = pb0.w;               \
        Bs[BF][kq+0][64+mm] = pb1.x; Bs[BF][kq+1][64+mm] = pb1.y;               \
        Bs[BF][kq+2][64+mm] = pb1.z; Bs[BF][kq+3][64+mm] = pb1.w;               \
    } while (0)

    float acc[8][8];
#pragma unroll
    for (int i = 0; i < 8; i++)
#pragma unroll
        for (int j = 0; j < 8; j++) acc[i][j] = 0.0f;

    LDTILE(0);
    STTILE(0);
    __syncthreads();

    int buf = 0;
#pragma unroll 1
    for (int k0 = 0; k0 < KDIM; k0 += 16) {
        if (k0 + 16 < KDIM) LDTILE(k0 + 16);   // prefetch next tile to regs

#pragma unroll
        for (int k = 0; k < 16; k++) {
            float a[8], b[8];
            *(float4*)&a[0] = *(const float4*)&As[buf][k][tm];
            *(float4*)&a[4] = *(const float4*)&As[buf][k][tm + 4];
            *(float4*)&b[0] = *(const float4*)&Bs[buf][k][tn];
            *(float4*)&b[4] = *(const float4*)&Bs[buf][k][tn + 4];
#pragma unroll
            for (int i = 0; i < 8; i++)
#pragma unroll
                for (int j = 0; j < 8; j++)
                    acc[i][j] = fmaf(a[i], b[j], acc[i][j]);
        }

        if (k0 + 16 < KDIM) STTILE(buf ^ 1);   // store into the other buffer
        __syncthreads();
        buf ^= 1;
    }
#undef LDTILE
#undef STTILE

    if (MODE == 0) {
#pragma unroll
        for (int i = 0; i < 8; i++) {
            int m = m0 + tm + i;
#pragma unroll
            for (int j = 0; j < 8; j++) {
                int n = n0 + tn + j;
                g_xg[(size_t)m * G4 + n] = acc[i][j] + ba[n] + bb[n];
            }
        }
    } else {
#pragma unroll
        for (int i = 0; i < 8; i++) {
            int m = m0 + tm + i;
            int t = m >> 6, b = m & 63;
            float* orow = outp + (size_t)(b * TSTEPS + t) * VOCAB;
#pragma unroll
            for (int j = 0; j < 8; j++) {
                int n = n0 + tn + j;
                if (n < VOCAB) orow[n] = acc[i][j] + ba[n];
            }
        }
    }
}

// ---------------- cheap grid barrier: 32 spread counters ----------------
// Arrivals hash over 32 counters (128B apart) -> ~8 serialized L2 atomics per
// counter instead of 256 on one. Thread 0 polls the 32-sum. Monotonic target.
__device__ __forceinline__ void gridbar(unsigned target)
{
    __syncthreads();
    if (threadIdx.x == 0) {
        __threadfence();
        atomicAdd(&g_ctr[(blockIdx.x & 31) << 5], 1u);
        unsigned s;
        do {
            s = 0;
#pragma unroll
            for (int i = 0; i < 32; i++) {
                unsigned v;
                asm volatile("ld.relaxed.gpu.u32 %0, [%1];" : "=r"(v) : "l"(&g_ctr[i << 5]));
                s += v;
            }
        } while (s < target);
        __threadfence();
    }
    __syncthreads();
}

// ---------------- kernel 3: persistent LSTM scan ----------------
// 256 blocks x 256 threads, 2 CTAs/SM (all co-resident on 148 SMs).
// Block (rg, ksp): rg = bid>>2 owns rows rg*32..rg*32+31, ksp = bid&3 owns
// K-window [ksp*128, ksp*128+128). Thread (r = tid&31, s = tid>>5): row
// rg*32+r, K-slice ksp*128+s*16.. (+16). w[16] register-resident for all steps.
// Per step: copy h window (contiguous 32KB memcpy thanks to transposed g_hd),
// compute -> smem partials (pad-65 rows: bank = (r+b)%32, conflict-free),
// intra-block reduce over the 8 sub-splits, write ONE gmem partial per
// (row,b) per ksp (2MB/step), barrier, cell-update phase, barrier.
__global__ __launch_bounds__(256, 2)
void lstm_scan(const float* __restrict__ Whh)
{
    extern __shared__ float sm[];
    float* h_s    = sm;             // [128][64]   k-major, 8192 floats
    float* part_s = sm + 8192;      // [8][32][65] pad-65 rows, 16640 floats

    const int tid = threadIdx.x;
    const int bid = blockIdx.x;
    const int rg  = bid >> 2;       // 0..63
    const int ksp = bid & 3;        // 0..3
    const int r   = tid & 31;
    const int s   = tid >> 5;       // 0..7
    const int grow  = rg * 32 + r;
    const int kbase = ksp * 128 + s * 16;

    float w[16];
    {
        const float4* wp = (const float4*)&Whh[(size_t)grow * HID + kbase];
#pragma unroll
        for (int i = 0; i < 4; i++) {
            float4 v = wp[i];
            w[4*i+0] = v.x; w[4*i+1] = v.y; w[4*i+2] = v.z; w[4*i+3] = v.w;
        }
    }

    // cell-update assignment (phase B): 128 cells per block
    const bool docell = (tid < 128);
    const int cid = bid * 128 + tid;      // valid when tid<128
    const int cb  = cid >> 9;             // batch
    const int cj  = cid & 511;            // hidden index
    float c_reg = 0.0f;
    unsigned target = 0;

    // ---- t = 0: gates = x_gates[0] only (h0 = 0)
    if (docell) {
        float v0 = g_xg[(size_t)cb * G4 + cj];
        float v1 = g_xg[(size_t)cb * G4 + 512  + cj];
        float v2 = g_xg[(size_t)cb * G4 + 1024 + cj];
        float v3 = g_xg[(size_t)cb * G4 + 1536 + cj];
        float i_ = sigf(v0), f_ = sigf(v1), gt = tanhf(v2), o_ = sigf(v3);
        c_reg = f_ * c_reg + i_ * gt;
        float h = o_ * tanhf(c_reg);
        g_hd[0][cj * BATCH + cb] = h;             // transposed current-h
        g_hs[(size_t)cb * HID + cj] = h;          // row-major history
    }
    target += 256; gridbar(target);

#pragma unroll 1
    for (int t = 1; t < TSTEPS; t++) {
        // ---- phase A: load h window (contiguous), compute partial gates
        {
            const float4* hin = (const float4*)(&g_hd[(t - 1) & 1][ksp * 128 * BATCH]);
            float4* hs4 = (float4*)h_s;
#pragma unroll
            for (int i = 0; i < 8; i++)
                hs4[tid + i * 256] = hin[tid + i * 256];
        }
        __syncthreads();

        float acc[64];
#pragma unroll
        for (int b = 0; b < 64; b++) acc[b] = 0.0f;
#pragma unroll
        for (int kk = 0; kk < 16; kk++) {
            const float4* hrow = (const float4*)&h_s[(s * 16 + kk) * 64];
            float wv = w[kk];
#pragma unroll
            for (int b4 = 0; b4 < 16; b4++) {
                float4 h4 = hrow[b4];               // full-warp broadcast
                acc[b4*4+0] = fmaf(wv, h4.x, acc[b4*4+0]);
                acc[b4*4+1] = fmaf(wv, h4.y, acc[b4*4+1]);
                acc[b4*4+2] = fmaf(wv, h4.z, acc[b4*4+2]);
                acc[b4*4+3] = fmaf(wv, h4.w, acc[b4*4+3]);
            }
        }
        // partials -> smem (pad-65: bank = (r+b)%32, lanes have distinct r)
        {
            float* ps = &part_s[(s * 32 + r) * 65];
#pragma unroll
            for (int b = 0; b < 64; b++) ps[b] = acc[b];
        }
        __syncthreads();

        // ---- intra-block reduce over the 8 sub-splits, write gmem partial
        {
            int rr = tid & 31, bc = tid >> 5;
            int growr = rg * 32 + rr;
            float* gp = &g_part[((size_t)ksp * G4 + growr) * 64];
#pragma unroll
            for (int bi = 0; bi < 8; bi++) {
                int b = bc * 8 + bi;
                float v = 0.0f;
#pragma unroll
                for (int ss = 0; ss < 8; ss++)
                    v += part_s[(ss * 32 + rr) * 65 + b];
                gp[b] = v;
            }
        }
        target += 256; gridbar(target);

        // ---- phase B: reduce 4 K-window partials + cell update
        if (docell) {
            float v[4];
#pragma unroll
            for (int gg = 0; gg < 4; gg++) {
                float sum = g_xg[((size_t)t * 64 + cb) * G4 + gg * 512 + cj];
#pragma unroll
                for (int p = 0; p < 4; p++)
                    sum += g_part[((size_t)p * G4 + gg * 512 + cj) * 64 + cb];
                v[gg] = sum;
            }
            float i_ = sigf(v[0]), f_ = sigf(v[1]), gt = tanhf(v[2]), o_ = sigf(v[3]);
            c_reg = f_ * c_reg + i_ * gt;
            float h = o_ * tanhf(c_reg);
            g_hd[t & 1][cj * BATCH + cb] = h;
            g_hs[((size_t)t * 64 + cb) * HID + cj] = h;
        }
        target += 256; gridbar(target);
    }
}

// ---------------- launch ----------------
extern "C" void kernel_launch(void* const* d_in, const int* in_sizes, int n_in,
                              void* d_out, int out_size)
{
    const float* feat = (const float*)d_in[0];
    const int*   cap  = (const int*)  d_in[1];
    const float* emb  = (const float*)d_in[2];
    const float* Wih  = (const float*)d_in[3];
    const float* Whh  = (const float*)d_in[4];
    const float* bih  = (const float*)d_in[5];
    const float* bhh  = (const float*)d_in[6];
    const float* Wfc  = (const float*)d_in[7];
    const float* bfc  = (const float*)d_in[8];
    float* out = (float*)d_out;
    (void)in_sizes; (void)n_in; (void)out_size;

    const int lstm_smem = (8192 + 8 * 32 * 65) * 4;   // 99,328 B
    cudaFuncSetAttribute(lstm_scan, cudaFuncAttributeMaxDynamicSharedMemorySize, lstm_smem);

    gather_k<<<1024, 256>>>(feat, cap, emb);

    gemm128<2048, 0><<<dim3(G4 / 128, MROWS / 128), 256>>>(Wih, bih, bhh, nullptr);

    lstm_scan<<<256, 256, lstm_smem>>>(Whh);

    gemm128<10000, 1><<<dim3((VOCAB + 127) / 128, MROWS / 128), 256>>>(Wfc, bfc, nullptr, out);
}

// round 7
// speedup vs baseline: 2.2873x; 1.5958x over previous
#include <cuda_runtime.h>
#include <cuda_bf16.h>
#include <cstdint>

#define EMBED  512
#define HID    512
#define G4     2048      // 4*HIDDEN
#define VOCAB  10000
#define BATCH  64
#define TSTEPS 32
#define MROWS  (TSTEPS*BATCH)   // 2048
#define KDIM   512

// ---------------- scratch (device globals: allocation-free) ----------------
__device__ __align__(16) __nv_bfloat16 g_xs_hi[MROWS*EMBED];
__device__ __align__(16) __nv_bfloat16 g_xs_lo[MROWS*EMBED];
__device__ __align__(16) __nv_bfloat16 g_hs_hi[MROWS*HID];
__device__ __align__(16) __nv_bfloat16 g_hs_lo[MROWS*HID];
__device__ __align__(16) __nv_bfloat16 g_wih_hi[G4*KDIM];
__device__ __align__(16) __nv_bfloat16 g_wih_lo[G4*KDIM];
__device__ __align__(16) __nv_bfloat16 g_wfc_hi[VOCAB*KDIM];
__device__ __align__(16) __nv_bfloat16 g_wfc_lo[VOCAB*KDIM];
__device__ float g_xg  [MROWS*G4];        // 16 MB  x_gates (+biases)
__device__ float g_hd  [2][HID*BATCH];    //        current h, TRANSPOSED [j][b], double-buffered
__device__ float g_part[4*G4*BATCH];      // 2 MB   K-window partials [ksp][row][b]
__device__ unsigned g_ctr[32*32];         // spread barrier counters (stride 128B)

__device__ __forceinline__ float sigf(float x) { return 1.0f / (1.0f + __expf(-x)); }

__device__ __forceinline__ uint32_t packbf(__nv_bfloat16 a, __nv_bfloat16 b) {
    unsigned short x = *(unsigned short*)&a, y = *(unsigned short*)&b;
    return (uint32_t)x | ((uint32_t)y << 16);
}

__device__ __forceinline__ uint32_t smem_u32(const void* p) {
    uint32_t a;
    asm("{ .reg .u64 t; cvta.to.shared.u64 t, %1; cvt.u32.u64 %0, t; }" : "=r"(a) : "l"(p));
    return a;
}

// cp.async (sm_80+ PTX — valid on plain sm_103 target)
#define CP_ASYNC16(dst_u32, src_ptr) \
    asm volatile("cp.async.cg.shared.global [%0], [%1], 16;" :: "r"(dst_u32), "l"(src_ptr))
#define CP_COMMIT()  asm volatile("cp.async.commit_group;" ::: "memory")
#define CP_WAIT1()   asm volatile("cp.async.wait_group 1;" ::: "memory")
#define CP_WAIT0()   asm volatile("cp.async.wait_group 0;" ::: "memory")

// HMMA m16n8k16 bf16 -> f32 (sm_80+ PTX)
__device__ __forceinline__ void mma_bf16(float* d, const uint32_t* a, const uint32_t* b) {
    asm volatile(
        "mma.sync.aligned.m16n8k16.row.col.f32.bf16.bf16.f32 "
        "{%0,%1,%2,%3}, {%4,%5,%6,%7}, {%8,%9}, {%0,%1,%2,%3};"
        : "+f"(d[0]), "+f"(d[1]), "+f"(d[2]), "+f"(d[3])
        : "r"(a[0]), "r"(a[1]), "r"(a[2]), "r"(a[3]), "r"(b[0]), "r"(b[1]));
}

__device__ __forceinline__ void split_store(uint2* hi, uint2* lo, int i, float4 v) {
    __nv_bfloat16 h0 = __float2bfloat16_rn(v.x), h1 = __float2bfloat16_rn(v.y);
    __nv_bfloat16 h2 = __float2bfloat16_rn(v.z), h3 = __float2bfloat16_rn(v.w);
    uint2 H; H.x = packbf(h0, h1); H.y = packbf(h2, h3);
    __nv_bfloat16 l0 = __float2bfloat16_rn(v.x - __bfloat162float(h0));
    __nv_bfloat16 l1 = __float2bfloat16_rn(v.y - __bfloat162float(h1));
    __nv_bfloat16 l2 = __float2bfloat16_rn(v.z - __bfloat162float(h2));
    __nv_bfloat16 l3 = __float2bfloat16_rn(v.w - __bfloat162float(h3));
    uint2 L; L.x = packbf(l0, l1); L.y = packbf(l2, l3);
    hi[i] = H; lo[i] = L;
}

// ---------------- kernel 0: split fp32 weights -> bf16 hi/lo ----------------
template<int WHICH>   // 0: W_ih -> g_wih_*,  1: W_fc -> g_wfc_*
__global__ void cvt_split(const float4* __restrict__ src, int n4)
{
    uint2* hi = (uint2*)(WHICH == 0 ? g_wih_hi : g_wfc_hi);
    uint2* lo = (uint2*)(WHICH == 0 ? g_wih_lo : g_wfc_lo);
    for (int i = blockIdx.x * blockDim.x + threadIdx.x; i < n4; i += gridDim.x * blockDim.x)
        split_store(hi, lo, i, src[i]);
}

// ---------------- kernel 1: gather xs -> bf16 hi/lo (also resets barrier counters) ----------------
__global__ void gather_k(const float* __restrict__ feat,
                         const int*   __restrict__ cap32,
                         const float* __restrict__ emb)
{
    if (blockIdx.x == 0) {
        for (int i = threadIdx.x; i < 32 * 32; i += 256) g_ctr[i] = 0u;
    }
    int idx = blockIdx.x * blockDim.x + threadIdx.x;   // float4 id, 262144 total
    int e4  = idx & (EMBED/4 - 1);
    int row = idx >> 7;
    int t = row >> 6, b = row & 63;
    const float4* src;
    if (t == 0) {
        src = (const float4*)(feat + b * EMBED);
    } else {
        // int64 little-endian: odd 32-bit words are zero (values in [0,10000))
        bool i64 = (cap32[1] == 0 && cap32[3] == 0 && cap32[5] == 0 && cap32[7] == 0);
        int ci = b * TSTEPS + (t - 1);
        int v  = i64 ? cap32[2 * ci] : cap32[ci];
        src = (const float4*)(emb + (long)v * EMBED);
    }
    split_store((uint2*)g_xs_hi, (uint2*)g_xs_lo, idx, src[e4]);
}

// ---------------- warp-MMA GEMM: C[2048, N] = A[2048,512] * B[N,512]^T (3-term bf16 split) ----------------
// Block tile 128x128, BK=32, 8 warps (2m x 4n), warp tile 64x32, m16n8k16 HMMA.
// smem rows padded to 40 bf16 (80B): row-stride 20 banks -> fragment loads conflict-free.
// cp.async double-buffered. MODE 0: C -> g_xg + bih + bhh. MODE 1: C -> out permuted (b,t,v) + bfc.
#define ROWP 40                       // padded row length in bf16
#define MATB (128*ROWP*2)             // 10240 B per matrix tile
#define GBUF (4*MATB)                 // 40960 B per buffer (AH,AL,BH,BL)
#define NCHUNK (KDIM/32)              // 16

__device__ __forceinline__ void issue_tile(uint32_t dst, const __nv_bfloat16* __restrict__ src,
                                           int row0, int rowmax, int kc, int tid)
{
#pragma unroll
    for (int i = 0; i < 2; i++) {
        int u = tid + i * 256;              // 0..511 : 128 rows x 4 x 16B
        int row = u >> 2, cu = u & 3;
        int r = row0 + row; if (r > rowmax) r = rowmax;   // clamp (epilogue guards cols)
        CP_ASYNC16(dst + row * (ROWP*2) + cu * 16,
                   src + (size_t)r * KDIM + kc + cu * 8);
    }
}

template<int BN, int MODE>
__global__ __launch_bounds__(256, 2)
void mma_gemm(const float* __restrict__ ba, const float* __restrict__ bb2,
              float* __restrict__ outp)
{
    extern __shared__ char dsm[];
    const __nv_bfloat16* Ahi = (MODE == 0) ? g_xs_hi : g_hs_hi;
    const __nv_bfloat16* Alo = (MODE == 0) ? g_xs_lo : g_hs_lo;
    const __nv_bfloat16* Bhi = (MODE == 0) ? g_wih_hi : g_wfc_hi;
    const __nv_bfloat16* Blo = (MODE == 0) ? g_wih_lo : g_wfc_lo;

    const int tid  = threadIdx.x;
    const int wid  = tid >> 5;
    const int lane = tid & 31;
    const int wm   = wid >> 2;          // 0..1  (64-row half)
    const int wn   = wid & 3;           // 0..3  (32-col quarter)
    const int gid  = lane >> 2;         // 0..7
    const int tig  = lane & 3;          // 0..3
    const int n0 = blockIdx.x * 128;
    const int m0 = blockIdx.y * 128;

    const uint32_t sbase = smem_u32(dsm);

    float acc[4][4][4];                 // [mi][ni][reg]
#pragma unroll
    for (int mi = 0; mi < 4; mi++)
#pragma unroll
        for (int ni = 0; ni < 4; ni++)
#pragma unroll
            for (int q = 0; q < 4; q++) acc[mi][ni][q] = 0.0f;

    // preload chunk 0 into buffer 0
    {
        uint32_t b0 = sbase;
        issue_tile(b0 + 0*MATB, Ahi, m0, MROWS - 1, 0, tid);
        issue_tile(b0 + 1*MATB, Alo, m0, MROWS - 1, 0, tid);
        issue_tile(b0 + 2*MATB, Bhi, n0, BN - 1, 0, tid);
        issue_tile(b0 + 3*MATB, Blo, n0, BN - 1, 0, tid);
        CP_COMMIT();
    }

#pragma unroll 1
    for (int c = 0; c < NCHUNK; c++) {
        if (c + 1 < NCHUNK) {
            uint32_t nb = sbase + ((c + 1) & 1) * GBUF;
            int kc = (c + 1) * 32;
            issue_tile(nb + 0*MATB, Ahi, m0, MROWS - 1, kc, tid);
            issue_tile(nb + 1*MATB, Alo, m0, MROWS - 1, kc, tid);
            issue_tile(nb + 2*MATB, Bhi, n0, BN - 1, kc, tid);
            issue_tile(nb + 3*MATB, Blo, n0, BN - 1, kc, tid);
            CP_COMMIT();
            CP_WAIT1();                 // chunk c complete (c+1 may be in flight)
        } else {
            CP_WAIT0();
        }
        __syncthreads();

        const char* buf = dsm + (c & 1) * GBUF;
        const uint32_t* AH32 = (const uint32_t*)(buf + 0*MATB);
        const uint32_t* AL32 = (const uint32_t*)(buf + 1*MATB);
        const uint32_t* BH32 = (const uint32_t*)(buf + 2*MATB);
        const uint32_t* BL32 = (const uint32_t*)(buf + 3*MATB);

#pragma unroll
        for (int ks = 0; ks < 2; ks++) {            // two k16 steps per BK=32
            const int ks2 = ks * 8;                 // b32 offset within padded row (20 b32)
            uint32_t afH[4][4], afL[4][4], bfH[4][2], bfL[4][2];
#pragma unroll
            for (int mi = 0; mi < 4; mi++) {
                int rbase = (wm * 64 + mi * 16 + gid) * 20 + ks2 + tig;
                afH[mi][0] = AH32[rbase];        afH[mi][1] = AH32[rbase + 160];
                afH[mi][2] = AH32[rbase + 4];    afH[mi][3] = AH32[rbase + 164];
                afL[mi][0] = AL32[rbase];        afL[mi][1] = AL32[rbase + 160];
                afL[mi][2] = AL32[rbase + 4];    afL[mi][3] = AL32[rbase + 164];
            }
#pragma unroll
            for (int ni = 0; ni < 4; ni++) {
                int rbase = (wn * 32 + ni * 8 + gid) * 20 + ks2 + tig;
                bfH[ni][0] = BH32[rbase];  bfH[ni][1] = BH32[rbase + 4];
                bfL[ni][0] = BL32[rbase];  bfL[ni][1] = BL32[rbase + 4];
            }
#pragma unroll
            for (int mi = 0; mi < 4; mi++)
#pragma unroll
                for (int ni = 0; ni < 4; ni++) {
                    mma_bf16(acc[mi][ni], afH[mi], bfH[ni]);
                    mma_bf16(acc[mi][ni], afH[mi], bfL[ni]);
                    mma_bf16(acc[mi][ni], afL[mi], bfH[ni]);
                }
        }
        __syncthreads();   // all reads of buf done before it is refilled (chunk c+2)
    }

    // ---- epilogue: d0,d1 -> row r, cols c..c+1; d2,d3 -> row r+8
#pragma unroll
    for (int mi = 0; mi < 4; mi++) {
        int r1 = m0 + wm * 64 + mi * 16 + gid;
#pragma unroll
        for (int half = 0; half < 2; half++) {
            int r = r1 + half * 8;
            float* orow;
            if (MODE == 0) {
                orow = g_xg + (size_t)r * G4;
            } else {
                int tt = r >> 6, bb_ = r & 63;
                orow = outp + (size_t)(bb_ * TSTEPS + tt) * VOCAB;
            }
#pragma unroll
            for (int ni = 0; ni < 4; ni++) {
                int cc = n0 + wn * 32 + ni * 8 + tig * 2;
                float2 v;
                v.x = acc[mi][ni][half * 2 + 0];
                v.y = acc[mi][ni][half * 2 + 1];
                if (MODE == 0) {
                    v.x += ba[cc]     + bb2[cc];
                    v.y += ba[cc + 1] + bb2[cc + 1];
                    *(float2*)(orow + cc) = v;
                } else if (cc < VOCAB) {      // cc even, VOCAB even -> pair fully in-bounds
                    v.x += ba[cc];
                    v.y += ba[cc + 1];
                    *(float2*)(orow + cc) = v;
                }
            }
        }
    }
}

// ---------------- cheap grid barrier: 32 spread counters ----------------
__device__ __forceinline__ void gridbar(unsigned target)
{
    __syncthreads();
    if (threadIdx.x == 0) {
        __threadfence();
        atomicAdd(&g_ctr[(blockIdx.x & 31) << 5], 1u);
        unsigned s;
        do {
            s = 0;
#pragma unroll
            for (int i = 0; i < 32; i++) {
                unsigned v;
                asm volatile("ld.relaxed.gpu.u32 %0, [%1];" : "=r"(v) : "l"(&g_ctr[i << 5]));
                s += v;
            }
        } while (s < target);
        __threadfence();
    }
    __syncthreads();
}

// ---------------- kernel 3: persistent LSTM scan ----------------
// 256 blocks x 256 threads, 2 CTAs/SM (all co-resident: grid barrier safe).
// Block (rg, ksp): rg owns 32 gate-rows, ksp a 128-wide K window. Thread:
// 2 rows x 32 batches x 16-K slice -> each h float4 feeds 8 FMAs (FMA-bound).
// Phase B reduces the 4 K-window partials, does the cell update with c in
// registers, emits h as fp32 (recurrence) + bf16 hi/lo (vocab GEMM input).
__global__ __launch_bounds__(256, 2)
void lstm_scan(const float* __restrict__ Whh)
{
    extern __shared__ float sm[];
    float* h_s    = sm;             // [128][64]   k-major, 8192 floats
    float* part_s = sm + 8192;      // [8][32][65] 16640 floats

    const int tid = threadIdx.x;
    const int bid = blockIdx.x;
    const int rg  = bid >> 2;       // 0..63
    const int ksp = bid & 3;        // 0..3
    const int rgrp = tid & 15;      // 2-row group
    const int bh   = (tid >> 4) & 1;
    const int ksl  = tid >> 5;      // 0..7
    const int row0 = rg * 32 + rgrp * 2;
    const int kbase = ksp * 128 + ksl * 16;

    float w[2][16];
#pragma unroll
    for (int rr = 0; rr < 2; rr++) {
        const float4* wp = (const float4*)&Whh[(size_t)(row0 + rr) * HID + kbase];
#pragma unroll
        for (int i = 0; i < 4; i++) {
            float4 v = wp[i];
            w[rr][4*i+0] = v.x; w[rr][4*i+1] = v.y; w[rr][4*i+2] = v.z; w[rr][4*i+3] = v.w;
        }
    }

    const bool docell = (tid < 128);
    const int cid = bid * 128 + tid;
    const int cb  = cid >> 9;
    const int cj  = cid & 511;
    float c_reg = 0.0f;
    unsigned target = 0;

    // t = 0: gates = x_gates[0] only (h0 = 0)
    if (docell) {
        float v0 = g_xg[(size_t)cb * G4 + cj];
        float v1 = g_xg[(size_t)cb * G4 + 512  + cj];
        float v2 = g_xg[(size_t)cb * G4 + 1024 + cj];
        float v3 = g_xg[(size_t)cb * G4 + 1536 + cj];
        float i_ = sigf(v0), f_ = sigf(v1), gt = tanhf(v2), o_ = sigf(v3);
        c_reg = f_ * c_reg + i_ * gt;
        float h = o_ * tanhf(c_reg);
        g_hd[0][cj * BATCH + cb] = h;
        __nv_bfloat16 hh = __float2bfloat16_rn(h);
        g_hs_hi[(size_t)cb * HID + cj] = hh;
        g_hs_lo[(size_t)cb * HID + cj] = __float2bfloat16_rn(h - __bfloat162float(hh));
    }
    target += 256; gridbar(target);

#pragma unroll 1
    for (int t = 1; t < TSTEPS; t++) {
        // phase A: copy h window (contiguous 32KB), compute partial gates
        {
            const float4* hin = (const float4*)(&g_hd[(t - 1) & 1][ksp * 128 * BATCH]);
            float4* hs4 = (float4*)h_s;
#pragma unroll
            for (int i = 0; i < 8; i++)
                hs4[tid + i * 256] = hin[tid + i * 256];
        }
        __syncthreads();

        float acc[2][32];
#pragma unroll
        for (int rr = 0; rr < 2; rr++)
#pragma unroll
            for (int b = 0; b < 32; b++) acc[rr][b] = 0.0f;
#pragma unroll
        for (int kk = 0; kk < 16; kk++) {
            const float4* hrow = (const float4*)&h_s[(ksl * 16 + kk) * 64 + bh * 32];
            float w0 = w[0][kk], w1 = w[1][kk];
#pragma unroll
            for (int b4 = 0; b4 < 8; b4++) {
                float4 h4 = hrow[b4];
                acc[0][b4*4+0] = fmaf(w0, h4.x, acc[0][b4*4+0]);
                acc[0][b4*4+1] = fmaf(w0, h4.y, acc[0][b4*4+1]);
                acc[0][b4*4+2] = fmaf(w0, h4.z, acc[0][b4*4+2]);
                acc[0][b4*4+3] = fmaf(w0, h4.w, acc[0][b4*4+3]);
                acc[1][b4*4+0] = fmaf(w1, h4.x, acc[1][b4*4+0]);
                acc[1][b4*4+1] = fmaf(w1, h4.y, acc[1][b4*4+1]);
                acc[1][b4*4+2] = fmaf(w1, h4.z, acc[1][b4*4+2]);
                acc[1][b4*4+3] = fmaf(w1, h4.w, acc[1][b4*4+3]);
            }
        }
#pragma unroll
        for (int rr = 0; rr < 2; rr++) {
            float* ps = &part_s[(ksl * 32 + rgrp * 2 + rr) * 65 + bh * 32];
#pragma unroll
            for (int b = 0; b < 32; b++) ps[b] = acc[rr][b];
        }
        __syncthreads();

        // intra-block reduce over 8 K-subslices, one gmem partial per (row,b)
        {
            int rr = tid & 31, bc = tid >> 5;
            int growr = rg * 32 + rr;
            float* gp = &g_part[((size_t)ksp * G4 + growr) * 64];
#pragma unroll
            for (int bi = 0; bi < 8; bi++) {
                int b = bc * 8 + bi;
                float v = 0.0f;
#pragma unroll
                for (int ss = 0; ss < 8; ss++)
                    v += part_s[(ss * 32 + rr) * 65 + b];
                gp[b] = v;
            }
        }
        target += 256; gridbar(target);

        // phase B: reduce 4 K-window partials + cell update
        if (docell) {
            float v[4];
#pragma unroll
            for (int gg = 0; gg < 4; gg++) {
                float sum = g_xg[((size_t)t * 64 + cb) * G4 + gg * 512 + cj];
#pragma unroll
                for (int p = 0; p < 4; p++)
                    sum += g_part[((size_t)p * G4 + gg * 512 + cj) * 64 + cb];
                v[gg] = sum;
            }
            float i_ = sigf(v[0]), f_ = sigf(v[1]), gt = tanhf(v[2]), o_ = sigf(v[3]);
            c_reg = f_ * c_reg + i_ * gt;
            float h = o_ * tanhf(c_reg);
            g_hd[t & 1][cj * BATCH + cb] = h;
            __nv_bfloat16 hh = __float2bfloat16_rn(h);
            g_hs_hi[((size_t)t * 64 + cb) * HID + cj] = hh;
            g_hs_lo[((size_t)t * 64 + cb) * HID + cj] = __float2bfloat16_rn(h - __bfloat162float(hh));
        }
        target += 256; gridbar(target);
    }
}

// ---------------- launch ----------------
extern "C" void kernel_launch(void* const* d_in, const int* in_sizes, int n_in,
                              void* d_out, int out_size)
{
    const float* feat = (const float*)d_in[0];
    const int*   cap  = (const int*)  d_in[1];
    const float* emb  = (const float*)d_in[2];
    const float* Wih  = (const float*)d_in[3];
    const float* Whh  = (const float*)d_in[4];
    const float* bih  = (const float*)d_in[5];
    const float* bhh  = (const float*)d_in[6];
    const float* Wfc  = (const float*)d_in[7];
    const float* bfc  = (const float*)d_in[8];
    float* out = (float*)d_out;
    (void)in_sizes; (void)n_in; (void)out_size;

    const int lstm_smem = (8192 + 8 * 32 * 65) * 4;   // 99,328 B
    const int mma_smem  = 2 * GBUF;                   // 81,920 B
    cudaFuncSetAttribute(lstm_scan, cudaFuncAttributeMaxDynamicSharedMemorySize, lstm_smem);
    cudaFuncSetAttribute(mma_gemm<G4, 0>,    cudaFuncAttributeMaxDynamicSharedMemorySize, mma_smem);
    cudaFuncSetAttribute(mma_gemm<VOCAB, 1>, cudaFuncAttributeMaxDynamicSharedMemorySize, mma_smem);

    cvt_split<0><<<512, 256>>>((const float4*)Wih, G4 * KDIM / 4);
    cvt_split<1><<<2048, 256>>>((const float4*)Wfc, VOCAB * KDIM / 4);

    gather_k<<<1024, 256>>>(feat, cap, emb);

    mma_gemm<G4, 0><<<dim3(G4 / 128, MROWS / 128), 256, mma_smem>>>(bih, bhh, nullptr);

    lstm_scan<<<256, 256, lstm_smem>>>(Whh);

    mma_gemm<VOCAB, 1><<<dim3((VOCAB + 127) / 128, MROWS / 128), 256, mma_smem>>>(bfc, nullptr, out);
}

// round 15
// speedup vs baseline: 3.5295x; 1.5431x over previous
#include <cuda_runtime.h>
#include <cuda_bf16.h>
#include <cstdint>

#define EMBED  512
#define HID    512
#define G4     2048      // 4*HIDDEN
#define VOCAB  10000
#define BATCH  64
#define TSTEPS 32
#define MROWS  (TSTEPS*BATCH)   // 2048
#define KDIM   512

// ---------------- scratch (device globals: allocation-free) ----------------
__device__ __align__(16) __nv_bfloat16 g_xs_hi[MROWS*EMBED];
__device__ __align__(16) __nv_bfloat16 g_xs_lo[MROWS*EMBED];
__device__ __align__(16) __nv_bfloat16 g_hs_hi[MROWS*HID];
__device__ __align__(16) __nv_bfloat16 g_hs_lo[MROWS*HID];
__device__ __align__(16) __nv_bfloat16 g_wih_hi[G4*KDIM];
__device__ __align__(16) __nv_bfloat16 g_wih_lo[G4*KDIM];
__device__ __align__(16) __nv_bfloat16 g_wfc_hi[VOCAB*KDIM];
__device__ __align__(16) __nv_bfloat16 g_wfc_lo[VOCAB*KDIM];
__device__ __align__(16) __nv_bfloat16 g_whh_hi[G4*HID];
__device__ __align__(16) __nv_bfloat16 g_whh_lo[G4*HID];
__device__ __align__(16) __nv_bfloat16 g_hb_hi[2][BATCH*HID];  // current h [b][j], DOUBLE-BUFFERED
__device__ __align__(16) __nv_bfloat16 g_hb_lo[2][BATCH*HID];
__device__ float g_xg [MROWS*G4];         // 16 MB  x_gates (+biases)
__device__ unsigned g_ctr[32*32];         // spread barrier counters (stride 128B)

__device__ __forceinline__ float sigf(float x) { return 1.0f / (1.0f + __expf(-x)); }

__device__ __forceinline__ uint32_t packbf(__nv_bfloat16 a, __nv_bfloat16 b) {
    unsigned short x = *(unsigned short*)&a, y = *(unsigned short*)&b;
    return (uint32_t)x | ((uint32_t)y << 16);
}

__device__ __forceinline__ uint32_t smem_u32(const void* p) {
    uint32_t a;
    asm("{ .reg .u64 t; cvta.to.shared.u64 t, %1; cvt.u32.u64 %0, t; }" : "=r"(a) : "l"(p));
    return a;
}

// cp.async (sm_80+ PTX — valid on plain sm_103 target)
#define CP_ASYNC16(dst_u32, src_ptr) \
    asm volatile("cp.async.cg.shared.global [%0], [%1], 16;" :: "r"(dst_u32), "l"(src_ptr))
#define CP_COMMIT()  asm volatile("cp.async.commit_group;" ::: "memory")
#define CP_WAIT1()   asm volatile("cp.async.wait_group 1;" ::: "memory")
#define CP_WAIT0()   asm volatile("cp.async.wait_group 0;" ::: "memory")

// HMMA m16n8k16 bf16 -> f32 (sm_80+ PTX); fragment mapping verified in round 7
__device__ __forceinline__ void mma_bf16(float* d, const uint32_t* a, const uint32_t* b) {
    asm volatile(
        "mma.sync.aligned.m16n8k16.row.col.f32.bf16.bf16.f32 "
        "{%0,%1,%2,%3}, {%4,%5,%6,%7}, {%8,%9}, {%0,%1,%2,%3};"
        : "+f"(d[0]), "+f"(d[1]), "+f"(d[2]), "+f"(d[3])
        : "r"(a[0]), "r"(a[1]), "r"(a[2]), "r"(a[3]), "r"(b[0]), "r"(b[1]));
}

__device__ __forceinline__ void split_store(uint2* hi, uint2* lo, int i, float4 v) {
    __nv_bfloat16 h0 = __float2bfloat16_rn(v.x), h1 = __float2bfloat16_rn(v.y);
    __nv_bfloat16 h2 = __float2bfloat16_rn(v.z), h3 = __float2bfloat16_rn(v.w);
    uint2 H; H.x = packbf(h0, h1); H.y = packbf(h2, h3);
    __nv_bfloat16 l0 = __float2bfloat16_rn(v.x - __bfloat162float(h0));
    __nv_bfloat16 l1 = __float2bfloat16_rn(v.y - __bfloat162float(h1));
    __nv_bfloat16 l2 = __float2bfloat16_rn(v.z - __bfloat162float(h2));
    __nv_bfloat16 l3 = __float2bfloat16_rn(v.w - __bfloat162float(h3));
    uint2 L; L.x = packbf(l0, l1); L.y = packbf(l2, l3);
    hi[i] = H; lo[i] = L;
}

// ---------------- kernel 0: split fp32 weights -> bf16 hi/lo ----------------
template<int WHICH>   // 0: W_ih, 1: W_fc, 2: W_hh
__global__ void cvt_split(const float4* __restrict__ src, int n4)
{
    uint2* hi = (uint2*)(WHICH == 0 ? g_wih_hi : (WHICH == 1 ? g_wfc_hi : g_whh_hi));
    uint2* lo = (uint2*)(WHICH == 0 ? g_wih_lo : (WHICH == 1 ? g_wfc_lo : g_whh_lo));
    for (int i = blockIdx.x * blockDim.x + threadIdx.x; i < n4; i += gridDim.x * blockDim.x)
        split_store(hi, lo, i, src[i]);
}

// ---------------- kernel 1: gather xs -> bf16 hi/lo (also resets barrier counters) ----------------
__global__ void gather_k(const float* __restrict__ feat,
                         const int*   __restrict__ cap32,
                         const float* __restrict__ emb)
{
    if (blockIdx.x == 0) {
        for (int i = threadIdx.x; i < 32 * 32; i += 256) g_ctr[i] = 0u;
    }
    int idx = blockIdx.x * blockDim.x + threadIdx.x;   // float4 id, 262144 total
    int e4  = idx & (EMBED/4 - 1);
    int row = idx >> 7;
    int t = row >> 6, b = row & 63;
    const float4* src;
    if (t == 0) {
        src = (const float4*)(feat + b * EMBED);
    } else {
        // int64 little-endian: odd 32-bit words are zero (values in [0,10000))
        bool i64 = (cap32[1] == 0 && cap32[3] == 0 && cap32[5] == 0 && cap32[7] == 0);
        int ci = b * TSTEPS + (t - 1);
        int v  = i64 ? cap32[2 * ci] : cap32[ci];
        src = (const float4*)(emb + (long)v * EMBED);
    }
    split_store((uint2*)g_xs_hi, (uint2*)g_xs_lo, idx, src[e4]);
}

// ---------------- warp-MMA GEMM: C[2048, N] = A[2048,512] * B[N,512]^T (3-term bf16 split) ----------------
// (unchanged from round 7: measured 264 TF/s effective)
#define ROWP 40
#define MATB (128*ROWP*2)
#define GBUF (4*MATB)
#define NCHUNK (KDIM/32)

__device__ __forceinline__ void issue_tile(uint32_t dst, const __nv_bfloat16* __restrict__ src,
                                           int row0, int rowmax, int kc, int tid)
{
#pragma unroll
    for (int i = 0; i < 2; i++) {
        int u = tid + i * 256;
        int row = u >> 2, cu = u & 3;
        int r = row0 + row; if (r > rowmax) r = rowmax;
        CP_ASYNC16(dst + row * (ROWP*2) + cu * 16,
                   src + (size_t)r * KDIM + kc + cu * 8);
    }
}

template<int BN, int MODE>
__global__ __launch_bounds__(256, 2)
void mma_gemm(const float* __restrict__ ba, const float* __restrict__ bb2,
              float* __restrict__ outp)
{
    extern __shared__ char dsm[];
    const __nv_bfloat16* Ahi = (MODE == 0) ? g_xs_hi : g_hs_hi;
    const __nv_bfloat16* Alo = (MODE == 0) ? g_xs_lo : g_hs_lo;
    const __nv_bfloat16* Bhi = (MODE == 0) ? g_wih_hi : g_wfc_hi;
    const __nv_bfloat16* Blo = (MODE == 0) ? g_wih_lo : g_wfc_lo;

    const int tid  = threadIdx.x;
    const int wid  = tid >> 5;
    const int lane = tid & 31;
    const int wm   = wid >> 2;
    const int wn   = wid & 3;
    const int gid  = lane >> 2;
    const int tig  = lane & 3;
    const int n0 = blockIdx.x * 128;
    const int m0 = blockIdx.y * 128;

    const uint32_t sbase = smem_u32(dsm);

    float acc[4][4][4];
#pragma unroll
    for (int mi = 0; mi < 4; mi++)
#pragma unroll
        for (int ni = 0; ni < 4; ni++)
#pragma unroll
            for (int q = 0; q < 4; q++) acc[mi][ni][q] = 0.0f;

    {
        uint32_t b0 = sbase;
        issue_tile(b0 + 0*MATB, Ahi, m0, MROWS - 1, 0, tid);
        issue_tile(b0 + 1*MATB, Alo, m0, MROWS - 1, 0, tid);
        issue_tile(b0 + 2*MATB, Bhi, n0, BN - 1, 0, tid);
        issue_tile(b0 + 3*MATB, Blo, n0, BN - 1, 0, tid);
        CP_COMMIT();
    }

#pragma unroll 1
    for (int c = 0; c < NCHUNK; c++) {
        if (c + 1 < NCHUNK) {
            uint32_t nb = sbase + ((c + 1) & 1) * GBUF;
            int kc = (c + 1) * 32;
            issue_tile(nb + 0*MATB, Ahi, m0, MROWS - 1, kc, tid);
            issue_tile(nb + 1*MATB, Alo, m0, MROWS - 1, kc, tid);
            issue_tile(nb + 2*MATB, Bhi, n0, BN - 1, kc, tid);
            issue_tile(nb + 3*MATB, Blo, n0, BN - 1, kc, tid);
            CP_COMMIT();
            CP_WAIT1();
        } else {
            CP_WAIT0();
        }
        __syncthreads();

        const char* buf = dsm + (c & 1) * GBUF;
        const uint32_t* AH32 = (const uint32_t*)(buf + 0*MATB);
        const uint32_t* AL32 = (const uint32_t*)(buf + 1*MATB);
        const uint32_t* BH32 = (const uint32_t*)(buf + 2*MATB);
        const uint32_t* BL32 = (const uint32_t*)(buf + 3*MATB);

#pragma unroll
        for (int ks = 0; ks < 2; ks++) {
            const int ks2 = ks * 8;
            uint32_t afH[4][4], afL[4][4], bfH[4][2], bfL[4][2];
#pragma unroll
            for (int mi = 0; mi < 4; mi++) {
                int rbase = (wm * 64 + mi * 16 + gid) * 20 + ks2 + tig;
                afH[mi][0] = AH32[rbase];        afH[mi][1] = AH32[rbase + 160];
                afH[mi][2] = AH32[rbase + 4];    afH[mi][3] = AH32[rbase + 164];
                afL[mi][0] = AL32[rbase];        afL[mi][1] = AL32[rbase + 160];
                afL[mi][2] = AL32[rbase + 4];    afL[mi][3] = AL32[rbase + 164];
            }
#pragma unroll
            for (int ni = 0; ni < 4; ni++) {
                int rbase = (wn * 32 + ni * 8 + gid) * 20 + ks2 + tig;
                bfH[ni][0] = BH32[rbase];  bfH[ni][1] = BH32[rbase + 4];
                bfL[ni][0] = BL32[rbase];  bfL[ni][1] = BL32[rbase + 4];
            }
#pragma unroll
            for (int mi = 0; mi < 4; mi++)
#pragma unroll
                for (int ni = 0; ni < 4; ni++) {
                    mma_bf16(acc[mi][ni], afH[mi], bfH[ni]);
                    mma_bf16(acc[mi][ni], afH[mi], bfL[ni]);
                    mma_bf16(acc[mi][ni], afL[mi], bfH[ni]);
                }
        }
        __syncthreads();
    }

#pragma unroll
    for (int mi = 0; mi < 4; mi++) {
        int r1 = m0 + wm * 64 + mi * 16 + gid;
#pragma unroll
        for (int half = 0; half < 2; half++) {
            int r = r1 + half * 8;
            float* orow;
            if (MODE == 0) {
                orow = g_xg + (size_t)r * G4;
            } else {
                int tt = r >> 6, bb_ = r & 63;
                orow = outp + (size_t)(bb_ * TSTEPS + tt) * VOCAB;
            }
#pragma unroll
            for (int ni = 0; ni < 4; ni++) {
                int cc = n0 + wn * 32 + ni * 8 + tig * 2;
                float2 v;
                v.x = acc[mi][ni][half * 2 + 0];
                v.y = acc[mi][ni][half * 2 + 1];
                if (MODE == 0) {
                    v.x += ba[cc]     + bb2[cc];
                    v.y += ba[cc + 1] + bb2[cc + 1];
                    *(float2*)(orow + cc) = v;
                } else if (cc < VOCAB) {
                    v.x += ba[cc];
                    v.y += ba[cc + 1];
                    *(float2*)(orow + cc) = v;
                }
            }
        }
    }
}

// ---------------- cheap grid barrier: 32 spread counters ----------------
__device__ __forceinline__ void gridbar(unsigned target)
{
    __syncthreads();
    if (threadIdx.x == 0) {
        __threadfence();
        atomicAdd(&g_ctr[(blockIdx.x & 31) << 5], 1u);
        unsigned s;
        do {
            s = 0;
#pragma unroll
            for (int i = 0; i < 32; i++) {
                unsigned v;
                asm volatile("ld.relaxed.gpu.u32 %0, [%1];" : "=r"(v) : "l"(&g_ctr[i << 5]));
                s += v;
            }
        } while (s < target);
        __threadfence();
    }
    __syncthreads();
}

// ---------------- kernel 3: tensor-core persistent LSTM scan ----------------
// 128 blocks (32 j-slices x 4 b-slices) x 256 threads, 1 CTA/SM (smem ~105KB),
// all co-resident -> grid barrier safe. Block owns cells (16 batches x 16 j)
// and computes ALL FOUR gates for them with FULL K=512:
//   G[16 x 64] = h[b-slice,512] @ Whh[gate rows]^T, 3-term bf16 split.
// Gate rows = {g*512 + j0 + 0..15 : g=0..3}. No K-split, ONE barrier/step.
// c resident in registers (1 cell/thread). g_hb double-buffered by step
// parity (read (t-1)&1, write t&1) -> no same-step read/write race.
// Whh hi/lo streamed per step from L2 (4MB resident) in 4 double-buffered
// K=128 chunks; h slice (32KB hi+lo) loaded once per step via cp.async.
#define SC_AROW 260                    // b32 per padded A row (520 bf16)
#define SC_BROW 68                     // b32 per padded B row (136 bf16)
#define SC_AHI  0
#define SC_ALO  16640                  // 16*1040
#define SC_B0   33280
#define SC_BHIO 0
#define SC_BLOO 17408                  // 64*272
#define SC_BBUF 34816                  // Bhi+Blo per chunk buffer
#define SC_GS   (SC_B0 + 2*SC_BBUF)    // 102912
#define SC_SMEM (SC_GS + 16*68*4)      // 107264

__device__ __forceinline__ void scan_issue_b(uint32_t dstbase, int kc, int j0, int tid)
{
#pragma unroll
    for (int i = 0; i < 4; i++) {
        int u = tid + i * 256;             // 0..1023
        int rn = u >> 4, cu = u & 15;      // row 0..63, 16B-chunk 0..15
        int grow = ((rn >> 4) << 9) + j0 + (rn & 15);   // (rn/16)*512 + j0 + rn%16
        CP_ASYNC16(dstbase + SC_BHIO + rn * 272 + cu * 16,
                   g_whh_hi + (size_t)grow * HID + kc + cu * 8);
        CP_ASYNC16(dstbase + SC_BLOO + rn * 272 + cu * 16,
                   g_whh_lo + (size_t)grow * HID + kc + cu * 8);
    }
}

__global__ __launch_bounds__(256, 1)
void lstm_scan()
{
    extern __shared__ char sm[];
    const int tid  = threadIdx.x;
    const int bid  = blockIdx.x;
    const int js   = bid >> 2;          // 0..31
    const int bs   = bid & 3;           // 0..3
    const int j0   = js * 16;
    const int b0   = bs * 16;
    const int wid  = tid >> 5;          // 0..7 : n-tile (8 gate rows each)
    const int lane = tid & 31;
    const int gid  = lane >> 2;
    const int tig  = lane & 3;
    const uint32_t sb = smem_u32(sm);

    // cell ownership: 256 cells = 16 batches x 16 j
    const int bl = tid >> 4;            // local batch 0..15
    const int jl = tid & 15;            // local hidden 0..15
    const int cb = b0 + bl;
    const int cj = j0 + jl;
    float c_reg = 0.0f;
    unsigned target = 0;

    // ---- t = 0: gates = x_gates only (h0 = 0)
    {
        const float* xr = g_xg + (size_t)cb * G4;
        float v0 = xr[cj], v1 = xr[512 + cj], v2 = xr[1024 + cj], v3 = xr[1536 + cj];
        float i_ = sigf(v0), f_ = sigf(v1), gt = tanhf(v2), o_ = sigf(v3);
        c_reg = f_ * c_reg + i_ * gt;
        float h = o_ * tanhf(c_reg);
        __nv_bfloat16 hh = __float2bfloat16_rn(h);
        __nv_bfloat16 hl = __float2bfloat16_rn(h - __bfloat162float(hh));
        g_hb_hi[0][cb * HID + cj] = hh;  g_hb_lo[0][cb * HID + cj] = hl;
        g_hs_hi[(size_t)cb * HID + cj] = hh;
        g_hs_lo[(size_t)cb * HID + cj] = hl;
    }
    target += 128; gridbar(target);

#pragma unroll 1
    for (int t = 1; t < TSTEPS; t++) {
        const int rd = (t - 1) & 1, wr = t & 1;
        // ---- load A (h slice, 16 rows x 1024B, hi+lo) + B chunk 0
#pragma unroll
        for (int i = 0; i < 4; i++) {
            int u = tid + i * 256;
            int r = u >> 6, cu = u & 63;
            CP_ASYNC16(sb + SC_AHI + r * 1040 + cu * 16, g_hb_hi[rd] + (b0 + r) * HID + cu * 8);
            CP_ASYNC16(sb + SC_ALO + r * 1040 + cu * 16, g_hb_lo[rd] + (b0 + r) * HID + cu * 8);
        }
        scan_issue_b(sb + SC_B0, 0, j0, tid);
        CP_COMMIT();

        float acc[4] = {0.f, 0.f, 0.f, 0.f};
        const uint32_t* AH32 = (const uint32_t*)(sm + SC_AHI);
        const uint32_t* AL32 = (const uint32_t*)(sm + SC_ALO);

#pragma unroll 1
        for (int c = 0; c < 4; c++) {
            if (c + 1 < 4) {
                scan_issue_b(sb + SC_B0 + ((c + 1) & 1) * SC_BBUF, (c + 1) * 128, j0, tid);
                CP_COMMIT();
                CP_WAIT1();
            } else {
                CP_WAIT0();
            }
            __syncthreads();

            const char* bb = sm + SC_B0 + (c & 1) * SC_BBUF;
            const uint32_t* BH32 = (const uint32_t*)(bb + SC_BHIO);
            const uint32_t* BL32 = (const uint32_t*)(bb + SC_BLOO);

#pragma unroll
            for (int ks = 0; ks < 8; ks++) {
                int ka = c * 64 + ks * 8 + tig;     // b32 within full-K A row
                int kb = ks * 8 + tig;              // b32 within chunk B row
                uint32_t aH[4], aL[4], bH[2], bL[2];
                aH[0] = AH32[gid * SC_AROW + ka];       aH[1] = AH32[(gid + 8) * SC_AROW + ka];
                aH[2] = AH32[gid * SC_AROW + ka + 4];   aH[3] = AH32[(gid + 8) * SC_AROW + ka + 4];
                aL[0] = AL32[gid * SC_AROW + ka];       aL[1] = AL32[(gid + 8) * SC_AROW + ka];
                aL[2] = AL32[gid * SC_AROW + ka + 4];   aL[3] = AL32[(gid + 8) * SC_AROW + ka + 4];
                int rb = (wid * 8 + gid) * SC_BROW + kb;
                bH[0] = BH32[rb];  bH[1] = BH32[rb + 4];
                bL[0] = BL32[rb];  bL[1] = BL32[rb + 4];
                mma_bf16(acc, aH, bH);
                mma_bf16(acc, aH, bL);
                mma_bf16(acc, aL, bH);
            }
            __syncthreads();
        }

        // ---- stage accum to smem G [batch 16][gate-row 64] (stride 68 f32)
        {
            float* Gs = (float*)(sm + SC_GS);
            int col = wid * 8 + tig * 2;
            Gs[gid * 68 + col]           = acc[0];
            Gs[gid * 68 + col + 1]       = acc[1];
            Gs[(gid + 8) * 68 + col]     = acc[2];
            Gs[(gid + 8) * 68 + col + 1] = acc[3];
        }
        __syncthreads();

        // ---- cell update (1 cell/thread), write h hi/lo into buffer wr
        {
            const float* Gs = (const float*)(sm + SC_GS);
            const float* xr = g_xg + ((size_t)t * 64 + cb) * G4;
            float v0 = xr[cj]        + Gs[bl * 68 + jl];
            float v1 = xr[512 + cj]  + Gs[bl * 68 + 16 + jl];
            float v2 = xr[1024 + cj] + Gs[bl * 68 + 32 + jl];
            float v3 = xr[1536 + cj] + Gs[bl * 68 + 48 + jl];
            float i_ = sigf(v0), f_ = sigf(v1), gt = tanhf(v2), o_ = sigf(v3);
            c_reg = f_ * c_reg + i_ * gt;
            float h = o_ * tanhf(c_reg);
            __nv_bfloat16 hh = __float2bfloat16_rn(h);
            __nv_bfloat16 hl = __float2bfloat16_rn(h - __bfloat162float(hh));
            if (t + 1 < TSTEPS) {                       // last step's g_hb never read
                g_hb_hi[wr][cb * HID + cj] = hh;
                g_hb_lo[wr][cb * HID + cj] = hl;
            }
            g_hs_hi[((size_t)t * 64 + cb) * HID + cj] = hh;
            g_hs_lo[((size_t)t * 64 + cb) * HID + cj] = hl;
        }
        if (t + 1 < TSTEPS) { target += 128; gridbar(target); }
    }
}

// ---------------- launch ----------------
extern "C" void kernel_launch(void* const* d_in, const int* in_sizes, int n_in,
                              void* d_out, int out_size)
{
    const float* feat = (const float*)d_in[0];
    const int*   cap  = (const int*)  d_in[1];
    const float* emb  = (const float*)d_in[2];
    const float* Wih  = (const float*)d_in[3];
    const float* Whh  = (const float*)d_in[4];
    const float* bih  = (const float*)d_in[5];
    const float* bhh  = (const float*)d_in[6];
    const float* Wfc  = (const float*)d_in[7];
    const float* bfc  = (const float*)d_in[8];
    float* out = (float*)d_out;
    (void)in_sizes; (void)n_in; (void)out_size;

    const int mma_smem = 2 * GBUF;        // 81,920 B
    cudaFuncSetAttribute(lstm_scan, cudaFuncAttributeMaxDynamicSharedMemorySize, SC_SMEM);
    cudaFuncSetAttribute(mma_gemm<G4, 0>,    cudaFuncAttributeMaxDynamicSharedMemorySize, mma_smem);
    cudaFuncSetAttribute(mma_gemm<VOCAB, 1>, cudaFuncAttributeMaxDynamicSharedMemorySize, mma_smem);

    cvt_split<0><<<512, 256>>>((const float4*)Wih, G4 * KDIM / 4);
    cvt_split<2><<<512, 256>>>((const float4*)Whh, G4 * HID / 4);
    cvt_split<1><<<2048, 256>>>((const float4*)Wfc, VOCAB * KDIM / 4);

    gather_k<<<1024, 256>>>(feat, cap, emb);

    mma_gemm<G4, 0><<<dim3(G4 / 128, MROWS / 128), 256, mma_smem>>>(bih, bhh, nullptr);

    lstm_scan<<<128, 256, SC_SMEM>>>();

    mma_gemm<VOCAB, 1><<<dim3((VOCAB + 127) / 128, MROWS / 128), 256, mma_smem>>>(bfc, nullptr, out);
}